// round 5
// baseline (speedup 1.0000x reference)
#include <cuda_runtime.h>
#include <cuda_fp16.h>
#include <math.h>

#define BB   64
#define VV   2048
#define ENCD 128
#define TT   100
#define EMBD 256
#define DECD 512
#define ATTD 256
#define NVOC 29
#define XD   384   // EMB + ENC
#define NCH  16    // V-chunks of 128

#define PRED_OFF  0
#define ALPHA_OFF (BB*TT*NVOC)            // 185600
#define LEN_OFF   (ALPHA_OFF + BB*TT*VV)  // 13292800

// ---------------- scratch (device globals; no allocation allowed) ----------
__device__ __half g_enc_att_h[BB*VV*ATTD];  // 64 MB fp16
__device__ __half g_enc_h[BB*VV*ENCD];      // 32 MB fp16
__device__ float  g_hbuf[2][BB*DECD];
__device__ float  g_c[BB*DECD];
__device__ float  g_dec_att[BB*ATTD];
__device__ float  g_gate[BB*ENCD];
__device__ float  g_scores[BB*VV];
__device__ float  g_pmax[BB*NCH];
__device__ float  g_psum[BB*NCH];
__device__ float  g_awe_part[BB*NCH*ENCD];  // 512 KB
__device__ float  g_x[BB*XD];

__device__ __forceinline__ float sigf(float x) { return 1.f/(1.f+__expf(-x)); }

// ============================================================================
// Setup A: mean_enc -> h0,c0 ; lengths to out tail
// ============================================================================
__global__ void s_init(const float* __restrict__ enc, const int* __restrict__ lens,
                       const float* __restrict__ Wih_, const float* __restrict__ bih_,
                       const float* __restrict__ Wic_, const float* __restrict__ bic_,
                       float* __restrict__ out)
{
    int b = blockIdx.x, tid = threadIdx.x;
    __shared__ float red[16*128];
    __shared__ float mean[128];
    int vr = tid >> 5, l = tid & 31;

    float4 acc = make_float4(0.f,0.f,0.f,0.f);
    for (int v = vr; v < VV; v += 16) {
        float4 e = *(const float4*)&enc[((size_t)(b*VV + v))*ENCD + l*4];
        acc.x += e.x; acc.y += e.y; acc.z += e.z; acc.w += e.w;
    }
    *(float4*)&red[vr*128 + l*4] = acc;
    __syncthreads();
    if (tid < 128) {
        float s = 0.f;
        #pragma unroll
        for (int i = 0; i < 16; i++) s += red[i*128 + tid];
        mean[tid] = s * (1.f/(float)VV);
    }
    __syncthreads();
    float ha = bih_[tid], ca = bic_[tid];
    const float* wh = Wih_ + (size_t)tid*ENCD;
    const float* wc = Wic_ + (size_t)tid*ENCD;
    #pragma unroll 4
    for (int k = 0; k < ENCD; k++) {
        float mk = mean[k];
        ha += mk * wh[k];
        ca += mk * wc[k];
    }
    g_hbuf[0][b*DECD + tid] = ha;
    g_c[b*DECD + tid] = ca;
    if (tid == 0) out[LEN_OFF + b] = (float)lens[b];
}

// ============================================================================
// Setup B: enc_att(fp16) = enc @ W_enc.T + b_enc ; fp16 enc copy
// ============================================================================
#define EA_SMEM ((128*264 + 128*68)*4)
__global__ void __launch_bounds__(256)
s_encatt(const float* __restrict__ enc, const float* __restrict__ Wenc,
         const float* __restrict__ benc)
{
    extern __shared__ float sm[];
    float* Wt = sm;             // [128][264]
    float* Et = sm + 128*264;   // [128][68]
    int tid = threadIdx.x;
    int rowbase = blockIdx.x * 32;

    for (int i = tid; i < 256*128; i += 256) {
        int k = i & 127, a = i >> 7;
        Wt[k*264 + a] = Wenc[a*128 + k];
    }
    for (int i = tid; i < 32*128; i += 256) {
        int k = i & 127, r = i >> 7;
        Et[k*68 + r] = enc[(size_t)(rowbase + r)*128 + k];
    }
    __syncthreads();

    for (int i = tid; i < 32*128; i += 256) {
        int r = i >> 7, k = i & 127;
        g_enc_h[(size_t)(rowbase + r)*ENCD + k] = __float2half_rn(Et[k*68 + r]);
    }

    int tr = tid >> 5, ta = tid & 31;
    int r0 = tr*4, a0 = ta*8;
    float acc[4][8];
    #pragma unroll
    for (int i = 0; i < 4; i++)
        #pragma unroll
        for (int j = 0; j < 8; j++) acc[i][j] = 0.f;

    #pragma unroll 4
    for (int k = 0; k < 128; k++) {
        float4 rf = *(const float4*)&Et[k*68 + r0];
        float4 a4 = *(const float4*)&Wt[k*264 + a0];
        float4 b4 = *(const float4*)&Wt[k*264 + a0 + 4];
        float rr[4] = {rf.x, rf.y, rf.z, rf.w};
        float aa[8] = {a4.x,a4.y,a4.z,a4.w,b4.x,b4.y,b4.z,b4.w};
        #pragma unroll
        for (int i = 0; i < 4; i++)
            #pragma unroll
            for (int j = 0; j < 8; j++) acc[i][j] += rr[i]*aa[j];
    }
    float4 be0 = *(const float4*)&benc[a0];
    float4 be1 = *(const float4*)&benc[a0+4];
    float bb[8] = {be0.x,be0.y,be0.z,be0.w,be1.x,be1.y,be1.z,be1.w};
    #pragma unroll
    for (int i = 0; i < 4; i++) {
        size_t base = (size_t)(rowbase + r0 + i)*ATTD + a0;
        __half2 h[4];
        #pragma unroll
        for (int j = 0; j < 4; j++)
            h[j] = __floats2half2_rn(acc[i][2*j] + bb[2*j], acc[i][2*j+1] + bb[2*j+1]);
        *(uint4*)&g_enc_att_h[base] = *(uint4*)h;
    }
}

// ============================================================================
// K1: dec_att / gate / pred_{t-1}
// ============================================================================
__global__ void __launch_bounds__(256)
k1_head(int t,
        const float* __restrict__ Wdec, const float* __restrict__ bdec,
        const float* __restrict__ Wbeta, const float* __restrict__ bbeta,
        const float* __restrict__ Wfin, const float* __restrict__ bfin,
        const int* __restrict__ lens, float* __restrict__ out)
{
    __shared__ float hT[512*17];
    int tid = threadIdx.x;
    int p = t & 1;
    int bg = blockIdx.y;
    int rr = blockIdx.x*16 + (tid >> 4);
    int lane = tid & 15;
    int b = bg*16 + lane;

    const float* hsrc = g_hbuf[p];
    for (int i = tid; i < 16*512; i += 256) {
        int bl = i >> 9, k = i & 511;
        hT[k*17 + bl] = hsrc[(bg*16 + bl)*DECD + k];
    }
    __syncthreads();

    const float* wrow = nullptr; float bias = 0.f;
    if (rr < 256)      { wrow = Wdec  + (size_t)rr*DECD;       bias = bdec[rr]; }
    else if (rr < 384) { wrow = Wbeta + (size_t)(rr-256)*DECD; bias = bbeta[rr-256]; }
    else if (rr < 384+NVOC) { wrow = Wfin + (size_t)(rr-384)*DECD; bias = bfin[rr-384]; }

    if (wrow) {
        float acc = bias;
        #pragma unroll 4
        for (int k = 0; k < 512; k += 4) {
            float4 w = *(const float4*)&wrow[k];
            acc += w.x*hT[(k  )*17 + lane] + w.y*hT[(k+1)*17 + lane]
                 + w.z*hT[(k+2)*17 + lane] + w.w*hT[(k+3)*17 + lane];
        }
        if (rr < 256) {
            g_dec_att[b*ATTD + rr] = acc;
        } else if (rr < 384) {
            g_gate[b*ENCD + (rr-256)] = sigf(acc);
        } else {
            if (t > 0 && (t-1) < lens[b])
                out[PRED_OFF + ((size_t)b*TT + (t-1))*NVOC + (rr-384)] = acc;
        }
    }
}

// ============================================================================
// K2 fused: scores (fp16, half2 math, 4 rows in flight) -> chunk-local
//           softmax stats -> partial awe over this chunk (fp16 enc).
// grid(16,64), block 256 = 8 warps; each block owns 128 v-rows of one b.
// ============================================================================
__global__ void __launch_bounds__(256)
k2_scores(int t, const float* __restrict__ wfull, const int* __restrict__ lens)
{
    int b = blockIdx.y;
    if (t >= lens[b]) return;
    int tid = threadIdx.x;
    int warp = tid >> 5, l = tid & 31;
    int chunk = blockIdx.x;
    int vbase = chunk*128;

    __shared__ float sc[128];
    __shared__ float al[128];
    __shared__ float wred[8];
    __shared__ float red[8*128];

    int a0 = l*8;
    __half2 d2[4]; float w[8];
    {
        float4 dd0 = *(const float4*)&g_dec_att[b*ATTD + a0];
        float4 dd1 = *(const float4*)&g_dec_att[b*ATTD + a0 + 4];
        d2[0] = __floats2half2_rn(dd0.x, dd0.y);
        d2[1] = __floats2half2_rn(dd0.z, dd0.w);
        d2[2] = __floats2half2_rn(dd1.x, dd1.y);
        d2[3] = __floats2half2_rn(dd1.z, dd1.w);
        float4 ww0 = *(const float4*)&wfull[a0];
        float4 ww1 = *(const float4*)&wfull[a0 + 4];
        w[0]=ww0.x; w[1]=ww0.y; w[2]=ww0.z; w[3]=ww0.w;
        w[4]=ww1.x; w[5]=ww1.y; w[6]=ww1.z; w[7]=ww1.w;
    }
    const __half2 z2 = __float2half2_rn(0.f);
    const __half* ea = g_enc_att_h + ((size_t)(b*VV + vbase))*ATTD;

    // ---- Phase A: scores, 4 rows in flight per warp
    #pragma unroll
    for (int i = 0; i < 16; i += 4) {
        uint4 q[4];
        #pragma unroll
        for (int u = 0; u < 4; u++)
            q[u] = *(const uint4*)&ea[(size_t)((i+u)*8 + warp)*ATTD + a0];
        float s[4];
        #pragma unroll
        for (int u = 0; u < 4; u++) {
            const __half2* h = (const __half2*)&q[u];
            float acc = 0.f;
            #pragma unroll
            for (int j = 0; j < 4; j++) {
                __half2 v = __hmax2(__hadd2(h[j], d2[j]), z2);
                float2 f = __half22float2(v);
                acc += f.x*w[2*j] + f.y*w[2*j+1];
            }
            s[u] = acc;
        }
        #pragma unroll
        for (int o = 16; o; o >>= 1) {
            #pragma unroll
            for (int u = 0; u < 4; u++)
                s[u] += __shfl_xor_sync(0xffffffffu, s[u], o);
        }
        if (l == 0) {
            #pragma unroll
            for (int u = 0; u < 4; u++) sc[(i+u)*8 + warp] = s[u];
        }
    }
    __syncthreads();

    // ---- chunk max
    float m = (tid < 128) ? sc[tid] : -1e30f;
    #pragma unroll
    for (int o = 16; o; o >>= 1) m = fmaxf(m, __shfl_xor_sync(0xffffffffu, m, o));
    if (l == 0) wred[warp] = m;
    __syncthreads();
    float bmax = fmaxf(fmaxf(wred[0], wred[1]), fmaxf(wred[2], wred[3]));

    // ---- unnormalized weights + chunk expsum
    float e = 0.f;
    if (tid < 128) {
        e = __expf(sc[tid] - bmax);
        al[tid] = e;
        g_scores[b*VV + vbase + tid] = sc[tid];
    }
    #pragma unroll
    for (int o = 16; o; o >>= 1) e += __shfl_xor_sync(0xffffffffu, e, o);
    __syncthreads();           // wred reuse + al publish
    if (l == 0) wred[warp] = e;
    __syncthreads();

    // ---- Phase B: partial awe (weights al[], fp16 enc)
    const __half* eh = g_enc_h + ((size_t)(b*VV + vbase))*ENCD;
    float4 acc = make_float4(0.f,0.f,0.f,0.f);
    #pragma unroll 4
    for (int i = 0; i < 16; i++) {
        int r = i*8 + warp;
        float a = al[r];
        uint2 q = *(const uint2*)&eh[(size_t)r*ENCD + l*4];
        float2 e0 = __half22float2(((const __half2*)&q)[0]);
        float2 e1 = __half22float2(((const __half2*)&q)[1]);
        acc.x += a*e0.x; acc.y += a*e0.y; acc.z += a*e1.x; acc.w += a*e1.y;
    }
    *(float4*)&red[warp*128 + l*4] = acc;
    __syncthreads();
    if (tid < 128) {
        float s = 0.f;
        #pragma unroll
        for (int i = 0; i < 8; i++) s += red[i*128 + tid];
        g_awe_part[(b*NCH + chunk)*ENCD + tid] = s;
    }
    if (tid == 0) {
        float ss = 0.f;
        #pragma unroll
        for (int i = 0; i < 8; i++) ss += wred[i];
        g_pmax[b*NCH + chunk] = bmax;
        g_psum[b*NCH + chunk] = ss;
    }
}

// ============================================================================
// K5: combine stats -> alphas out, awe reduce (+gate), emb lookup -> x.
// grid(64), block 256.
// ============================================================================
__global__ void __launch_bounds__(256)
k5_x(int t, const int* __restrict__ captions, const float* __restrict__ embW,
     const int* __restrict__ lens, float* __restrict__ out)
{
    int b = blockIdx.x;
    if (t >= lens[b]) return;
    int tid = threadIdx.x;
    __shared__ float cf[NCH];

    float M = -1e30f;
    #pragma unroll
    for (int i = 0; i < NCH; i++) M = fmaxf(M, g_pmax[b*NCH + i]);
    float S = 0.f;
    #pragma unroll
    for (int i = 0; i < NCH; i++) S += g_psum[b*NCH + i] * __expf(g_pmax[b*NCH + i] - M);
    float inv = 1.f/S;
    if (tid < NCH) cf[tid] = __expf(g_pmax[b*NCH + tid] - M) * inv;
    __syncthreads();

    // alphas
    float* aout = out + ALPHA_OFF + ((size_t)b*TT + t)*VV;
    #pragma unroll
    for (int v = tid; v < VV; v += 256)
        aout[v] = __expf(g_scores[b*VV + v] - M) * inv;

    // x = [emb, gate*awe]
    if (tid < 128) {
        float s = 0.f;
        #pragma unroll
        for (int i = 0; i < NCH; i++) s += g_awe_part[(b*NCH + i)*ENCD + tid] * cf[i];
        g_x[b*XD + EMBD + tid] = s * g_gate[b*ENCD + tid];
    }
    int cap = captions[b*TT + t];
    g_x[b*XD + tid] = embW[cap*EMBD + tid];
}

// ============================================================================
// K6: LSTM cell.
// ============================================================================
__global__ void __launch_bounds__(256)
k6_lstm(int t,
        const float* __restrict__ Wih, const float* __restrict__ bih,
        const float* __restrict__ Whh, const float* __restrict__ bhh,
        const int* __restrict__ lens)
{
    int jc = blockIdx.x;
    int bh = blockIdx.y;
    int tid = threadIdx.x;
    int p = t & 1;
    int jbase = jc*8;
    int b0 = bh*32;

    if (t >= lens[b0]) {
        int jj = tid >> 5, bl = tid & 31;
        int idx = (b0 + bl)*DECD + jbase + jj;
        g_hbuf[1-p][idx] = g_hbuf[p][idx];
        return;
    }

    __shared__ float zt[128*36];
    __shared__ float ws[32*132];
    __shared__ float gs[32*33];

    int r = tid >> 3;
    int lane = tid & 7;
    int bl0 = lane*4;
    int grow = (r >> 3)*DECD + jbase + (r & 7);

    float acc0=0.f, acc1=0.f, acc2=0.f, acc3=0.f;
    const float* hsrc = g_hbuf[p];

    for (int kt = 0; kt < 7; kt++) {
        for (int i = tid; i < 32*128; i += 256) {
            int bl = i >> 7, k = i & 127;
            float v;
            if (kt < 3) v = g_x[(b0 + bl)*XD + kt*128 + k];
            else        v = hsrc[(b0 + bl)*DECD + (kt-3)*128 + k];
            zt[k*36 + bl] = v;
        }
        const float* Wp = (kt < 3) ? Wih : Whh;
        int kstride = (kt < 3) ? XD : DECD;
        int kb = (kt < 3) ? kt*128 : (kt-3)*128;
        for (int i = tid; i < 32*128; i += 256) {
            int rr2 = i >> 7, k = i & 127;
            int gr = (rr2 >> 3)*DECD + jbase + (rr2 & 7);
            ws[rr2*132 + k] = Wp[(size_t)gr*kstride + kb + k];
        }
        __syncthreads();
        #pragma unroll 4
        for (int k = 0; k < 128; k += 4) {
            float4 w4 = *(const float4*)&ws[r*132 + k];
            float4 za = *(const float4*)&zt[(k  )*36 + bl0];
            float4 zb = *(const float4*)&zt[(k+1)*36 + bl0];
            float4 zc = *(const float4*)&zt[(k+2)*36 + bl0];
            float4 zd = *(const float4*)&zt[(k+3)*36 + bl0];
            acc0 += w4.x*za.x + w4.y*zb.x + w4.z*zc.x + w4.w*zd.x;
            acc1 += w4.x*za.y + w4.y*zb.y + w4.z*zc.y + w4.w*zd.y;
            acc2 += w4.x*za.z + w4.y*zb.z + w4.z*zc.z + w4.w*zd.z;
            acc3 += w4.x*za.w + w4.y*zb.w + w4.z*zc.w + w4.w*zd.w;
        }
        __syncthreads();
    }
    float bias = bih[grow] + bhh[grow];
    gs[r*33 + bl0 + 0] = acc0 + bias;
    gs[r*33 + bl0 + 1] = acc1 + bias;
    gs[r*33 + bl0 + 2] = acc2 + bias;
    gs[r*33 + bl0 + 3] = acc3 + bias;
    __syncthreads();

    {
        int jj = tid >> 5, bl = tid & 31;
        int b = b0 + bl;
        int hidx = b*DECD + jbase + jj;
        if (t < lens[b]) {
            float gi = gs[( 0 + jj)*33 + bl];
            float gf = gs[( 8 + jj)*33 + bl];
            float gg = gs[(16 + jj)*33 + bl];
            float go = gs[(24 + jj)*33 + bl];
            float si = sigf(gi), sf = sigf(gf), so = sigf(go);
            float tg = tanhf(gg);
            float cn = sf * g_c[hidx] + si * tg;
            float hn = so * tanhf(cn);
            g_c[hidx] = cn;
            g_hbuf[1-p][hidx] = hn;
        } else {
            g_hbuf[1-p][hidx] = g_hbuf[p][hidx];
        }
    }
}

// ============================================================================
extern "C" void kernel_launch(void* const* d_in, const int* in_sizes, int n_in,
                              void* d_out, int out_size)
{
    const float* enc      = (const float*)d_in[0];
    const int*   captions = (const int*)  d_in[1];
    const int*   lens     = (const int*)  d_in[2];
    const float* embW     = (const float*)d_in[3];
    const float* Wenc     = (const float*)d_in[4];
    const float* benc     = (const float*)d_in[5];
    const float* Wdec     = (const float*)d_in[6];
    const float* bdec     = (const float*)d_in[7];
    const float* wfull    = (const float*)d_in[8];
    // d_in[9] = b_full : dropped (softmax shift-invariant)
    const float* Wih      = (const float*)d_in[10];
    const float* bih      = (const float*)d_in[11];
    const float* Whh      = (const float*)d_in[12];
    const float* bhh      = (const float*)d_in[13];
    const float* Winith   = (const float*)d_in[14];
    const float* binith   = (const float*)d_in[15];
    const float* Winitc   = (const float*)d_in[16];
    const float* binitc   = (const float*)d_in[17];
    const float* Wbeta    = (const float*)d_in[18];
    const float* bbeta    = (const float*)d_in[19];
    const float* Wfin     = (const float*)d_in[20];
    const float* bfin     = (const float*)d_in[21];
    float* out = (float*)d_out;

    cudaFuncSetAttribute(s_encatt, cudaFuncAttributeMaxDynamicSharedMemorySize, EA_SMEM);

    cudaMemsetAsync(d_out, 0, (size_t)out_size*sizeof(float), 0);

    s_init<<<BB, 512>>>(enc, lens, Winith, binith, Winitc, binitc, out);
    s_encatt<<<(BB*VV)/32, 256, EA_SMEM>>>(enc, Wenc, benc);

    for (int t = 0; t < TT; t++) {
        k1_head<<<dim3(26,4), 256>>>(t, Wdec, bdec, Wbeta, bbeta, Wfin, bfin, lens, out);
        k2_scores<<<dim3(NCH,BB), 256>>>(t, wfull, lens);
        k5_x<<<BB, 256>>>(t, captions, embW, lens, out);
        k6_lstm<<<dim3(64,2), 256>>>(t, Wih, bih, Whh, bhh, lens);
    }
    k1_head<<<dim3(26,4), 256>>>(TT, Wdec, bdec, Wbeta, bbeta, Wfin, bfin, lens, out);
}

// round 6
// speedup vs baseline: 1.0957x; 1.0957x over previous
#include <cuda_runtime.h>
#include <cuda_fp16.h>
#include <math.h>

#define BB   64
#define VV   2048
#define ENCD 128
#define TT   100
#define EMBD 256
#define DECD 512
#define ATTD 256
#define NVOC 29
#define XD   384   // EMB + ENC
#define CRANKS 8   // CTAs per cluster (one cluster per b)

#define PRED_OFF  0
#define ALPHA_OFF (BB*TT*NVOC)            // 185600
#define LEN_OFF   (ALPHA_OFF + BB*TT*VV)  // 13292800

// ---------------- scratch (device globals; no allocation allowed) ----------
__device__ __half g_enc_att_h[BB*VV*ATTD];  // 64 MB fp16
__device__ __half g_enc_h[BB*VV*ENCD];      // 32 MB fp16
__device__ float  g_hbuf[2][BB*DECD];
__device__ float  g_c[BB*DECD];
__device__ float  g_dec_att[BB*ATTD];
__device__ float  g_gate[BB*ENCD];
__device__ float  g_part[BB*CRANKS*ENCD];   // per-rank partial awe
__device__ float  g_psum[BB*CRANKS];        // per-rank exp-sum
__device__ float  g_x[BB*XD];

__device__ __forceinline__ float sigf(float x) { return 1.f/(1.f+__expf(-x)); }

#define CLUSTER_ARRIVE() asm volatile("barrier.cluster.arrive.aligned;" ::: "memory")
#define CLUSTER_WAIT()   asm volatile("barrier.cluster.wait.aligned;"   ::: "memory")

// ============================================================================
// Setup A: mean_enc -> h0,c0 ; lengths to out tail
// ============================================================================
__global__ void s_init(const float* __restrict__ enc, const int* __restrict__ lens,
                       const float* __restrict__ Wih_, const float* __restrict__ bih_,
                       const float* __restrict__ Wic_, const float* __restrict__ bic_,
                       float* __restrict__ out)
{
    int b = blockIdx.x, tid = threadIdx.x;
    __shared__ float red[16*128];
    __shared__ float mean[128];
    int vr = tid >> 5, l = tid & 31;

    float4 acc = make_float4(0.f,0.f,0.f,0.f);
    for (int v = vr; v < VV; v += 16) {
        float4 e = *(const float4*)&enc[((size_t)(b*VV + v))*ENCD + l*4];
        acc.x += e.x; acc.y += e.y; acc.z += e.z; acc.w += e.w;
    }
    *(float4*)&red[vr*128 + l*4] = acc;
    __syncthreads();
    if (tid < 128) {
        float s = 0.f;
        #pragma unroll
        for (int i = 0; i < 16; i++) s += red[i*128 + tid];
        mean[tid] = s * (1.f/(float)VV);
    }
    __syncthreads();
    float ha = bih_[tid], ca = bic_[tid];
    const float* wh = Wih_ + (size_t)tid*ENCD;
    const float* wc = Wic_ + (size_t)tid*ENCD;
    #pragma unroll 4
    for (int k = 0; k < ENCD; k++) {
        float mk = mean[k];
        ha += mk * wh[k];
        ca += mk * wc[k];
    }
    g_hbuf[0][b*DECD + tid] = ha;
    g_c[b*DECD + tid] = ca;
    if (tid == 0) out[LEN_OFF + b] = (float)lens[b];
}

// ============================================================================
// Setup B: enc_att(fp16) = enc @ W_enc.T + b_enc ; fp16 enc copy
// ============================================================================
#define EA_SMEM ((128*264 + 128*68)*4)
__global__ void __launch_bounds__(256)
s_encatt(const float* __restrict__ enc, const float* __restrict__ Wenc,
         const float* __restrict__ benc)
{
    extern __shared__ float sm[];
    float* Wt = sm;             // [128][264]
    float* Et = sm + 128*264;   // [128][68]
    int tid = threadIdx.x;
    int rowbase = blockIdx.x * 32;

    for (int i = tid; i < 256*128; i += 256) {
        int k = i & 127, a = i >> 7;
        Wt[k*264 + a] = Wenc[a*128 + k];
    }
    for (int i = tid; i < 32*128; i += 256) {
        int k = i & 127, r = i >> 7;
        Et[k*68 + r] = enc[(size_t)(rowbase + r)*128 + k];
    }
    __syncthreads();

    for (int i = tid; i < 32*128; i += 256) {
        int r = i >> 7, k = i & 127;
        g_enc_h[(size_t)(rowbase + r)*ENCD + k] = __float2half_rn(Et[k*68 + r]);
    }

    int tr = tid >> 5, ta = tid & 31;
    int r0 = tr*4, a0 = ta*8;
    float acc[4][8];
    #pragma unroll
    for (int i = 0; i < 4; i++)
        #pragma unroll
        for (int j = 0; j < 8; j++) acc[i][j] = 0.f;

    #pragma unroll 4
    for (int k = 0; k < 128; k++) {
        float4 rf = *(const float4*)&Et[k*68 + r0];
        float4 a4 = *(const float4*)&Wt[k*264 + a0];
        float4 b4 = *(const float4*)&Wt[k*264 + a0 + 4];
        float rr[4] = {rf.x, rf.y, rf.z, rf.w};
        float aa[8] = {a4.x,a4.y,a4.z,a4.w,b4.x,b4.y,b4.z,b4.w};
        #pragma unroll
        for (int i = 0; i < 4; i++)
            #pragma unroll
            for (int j = 0; j < 8; j++) acc[i][j] += rr[i]*aa[j];
    }
    float4 be0 = *(const float4*)&benc[a0];
    float4 be1 = *(const float4*)&benc[a0+4];
    float bb[8] = {be0.x,be0.y,be0.z,be0.w,be1.x,be1.y,be1.z,be1.w};
    #pragma unroll
    for (int i = 0; i < 4; i++) {
        size_t base = (size_t)(rowbase + r0 + i)*ATTD + a0;
        __half2 h[4];
        #pragma unroll
        for (int j = 0; j < 4; j++)
            h[j] = __floats2half2_rn(acc[i][2*j] + bb[2*j], acc[i][2*j+1] + bb[2*j+1]);
        *(uint4*)&g_enc_att_h[base] = *(uint4*)h;
    }
}

// ============================================================================
// Kernel A: per-b cluster of 8 CTAs.
//   P0: heads (dec_att/gate/pred_{t-1}) from h            [cluster.sync]
//   P1: scores -> exp -> partial awe for rank's 256 rows  [cluster.sync]
//   P2: combine sums -> alphas out -> x = [emb, gate*awe]
// grid(8, 64), block 256.  Active iff t <= len; t == len does pred only.
// ============================================================================
__global__ void __cluster_dims__(CRANKS,1,1) __launch_bounds__(256)
kA_step(int t,
        const float* __restrict__ Wdec, const float* __restrict__ bdec,
        const float* __restrict__ Wbeta, const float* __restrict__ bbeta,
        const float* __restrict__ Wfin, const float* __restrict__ bfin,
        const float* __restrict__ wfull,
        const int* __restrict__ captions, const float* __restrict__ embW,
        const int* __restrict__ lens, float* __restrict__ out)
{
    int b = blockIdx.y;
    int len = lens[b];
    if (t > len) return;                    // uniform per cluster
    bool pred_only = (t == len);
    int rank = blockIdx.x;
    int tid = threadIdx.x;
    int warp = tid >> 5, l = tid & 31;

    __shared__ float h[512];
    __shared__ float al[256];
    __shared__ float red[8*128];
    __shared__ float wred[8];

    // ---- load h(t-1)
    const float* hsrc = g_hbuf[t & 1] + b*DECD;
    h[tid]       = hsrc[tid];
    h[tid + 256] = hsrc[tid + 256];
    __syncthreads();

    // ---- P0: heads.  413 rows; rank owns [52r, 52r+52). group of 4 threads/row.
    {
        int g = tid >> 2, sub = tid & 3;
        int row_real = rank*52 + g;
        int row = row_real < 413 ? row_real : 412;
        const float* wrow; float bias; int kind;
        if (row < 256)      { wrow = Wdec  + (size_t)row*DECD;       bias = bdec[row];      kind = 0; }
        else if (row < 384) { wrow = Wbeta + (size_t)(row-256)*DECD; bias = bbeta[row-256]; kind = 1; }
        else                { wrow = Wfin  + (size_t)(row-384)*DECD; bias = bfin[row-384];  kind = 2; }

        float acc = 0.f;
        #pragma unroll 8
        for (int i = 0; i < 32; i++) {
            int k = sub*4 + i*16;
            float4 w  = *(const float4*)&wrow[k];
            float4 hz = *(const float4*)&h[k];
            acc += w.x*hz.x + w.y*hz.y + w.z*hz.z + w.w*hz.w;
        }
        acc += __shfl_xor_sync(0xffffffffu, acc, 1);
        acc += __shfl_xor_sync(0xffffffffu, acc, 2);
        if (sub == 0 && g < 52 && row_real < 413) {
            acc += bias;
            if (kind == 0)      g_dec_att[b*ATTD + row] = acc;
            else if (kind == 1) g_gate[b*ENCD + (row-256)] = sigf(acc);
            else if (t > 0)     out[PRED_OFF + ((size_t)b*TT + (t-1))*NVOC + (row-384)] = acc;
        }
    }
    if (pred_only) return;                  // uniform: no rank executes syncs
    __threadfence();
    CLUSTER_ARRIVE(); CLUSTER_WAIT();       // S1

    // ---- P1: scores + exp + partial awe for rows [rank*256, rank*256+256)
    int vbase = rank*256;
    int a0 = l*8;
    __half2 d2[4]; float w[8];
    {
        float da[8];
        #pragma unroll
        for (int j = 0; j < 8; j++) da[j] = __ldcg(&g_dec_att[b*ATTD + a0 + j]);
        d2[0] = __floats2half2_rn(da[0], da[1]);
        d2[1] = __floats2half2_rn(da[2], da[3]);
        d2[2] = __floats2half2_rn(da[4], da[5]);
        d2[3] = __floats2half2_rn(da[6], da[7]);
        float4 ww0 = *(const float4*)&wfull[a0];
        float4 ww1 = *(const float4*)&wfull[a0 + 4];
        w[0]=ww0.x; w[1]=ww0.y; w[2]=ww0.z; w[3]=ww0.w;
        w[4]=ww1.x; w[5]=ww1.y; w[6]=ww1.z; w[7]=ww1.w;
    }
    const __half2 z2 = __float2half2_rn(0.f);
    const __half* ea = g_enc_att_h + ((size_t)(b*VV + vbase))*ATTD;

    #pragma unroll
    for (int i = 0; i < 32; i += 4) {
        uint4 q[4];
        #pragma unroll
        for (int u = 0; u < 4; u++)
            q[u] = *(const uint4*)&ea[(size_t)((i+u)*8 + warp)*ATTD + a0];
        float s[4];
        #pragma unroll
        for (int u = 0; u < 4; u++) {
            const __half2* hh = (const __half2*)&q[u];
            float acc = 0.f;
            #pragma unroll
            for (int j = 0; j < 4; j++) {
                __half2 v = __hmax2(__hadd2(hh[j], d2[j]), z2);
                float2 f = __half22float2(v);
                acc += f.x*w[2*j] + f.y*w[2*j+1];
            }
            s[u] = acc;
        }
        #pragma unroll
        for (int o = 16; o; o >>= 1) {
            #pragma unroll
            for (int u = 0; u < 4; u++)
                s[u] += __shfl_xor_sync(0xffffffffu, s[u], o);
        }
        if (l == 0) {
            #pragma unroll
            for (int u = 0; u < 4; u++) al[(i+u)*8 + warp] = __expf(s[u]);
        }
    }
    __syncthreads();

    // rank's exp-sum
    {
        float e = al[tid];
        #pragma unroll
        for (int o = 16; o; o >>= 1) e += __shfl_xor_sync(0xffffffffu, e, o);
        if (l == 0) wred[warp] = e;
    }

    // partial awe over rank's 256 rows
    const __half* eh = g_enc_h + ((size_t)(b*VV + vbase))*ENCD;
    float4 acc = make_float4(0.f,0.f,0.f,0.f);
    #pragma unroll 4
    for (int i = 0; i < 32; i++) {
        int r = i*8 + warp;
        float a = al[r];
        uint2 q = *(const uint2*)&eh[(size_t)r*ENCD + l*4];
        float2 e0 = __half22float2(((const __half2*)&q)[0]);
        float2 e1 = __half22float2(((const __half2*)&q)[1]);
        acc.x += a*e0.x; acc.y += a*e0.y; acc.z += a*e1.x; acc.w += a*e1.y;
    }
    *(float4*)&red[warp*128 + l*4] = acc;
    __syncthreads();
    if (tid < 128) {
        float s = 0.f;
        #pragma unroll
        for (int i = 0; i < 8; i++) s += red[i*128 + tid];
        g_part[(b*CRANKS + rank)*ENCD + tid] = s;
    }
    if (tid == 0) {
        float ss = 0.f;
        #pragma unroll
        for (int i = 0; i < 8; i++) ss += wred[i];
        g_psum[b*CRANKS + rank] = ss;
    }
    __threadfence();
    CLUSTER_ARRIVE(); CLUSTER_WAIT();       // S2

    // ---- P2: combine -> alphas, x
    if (tid < CRANKS) wred[tid] = __ldcg(&g_psum[b*CRANKS + tid]);
    __syncthreads();
    float S = 0.f;
    #pragma unroll
    for (int i = 0; i < CRANKS; i++) S += wred[i];
    float invS = 1.f/S;

    out[ALPHA_OFF + ((size_t)b*TT + t)*VV + vbase + tid] = al[tid] * invS;

    if (tid < 16) {
        int dm = rank*16 + tid;
        float s = 0.f;
        #pragma unroll
        for (int r = 0; r < CRANKS; r++) s += __ldcg(&g_part[(b*CRANKS + r)*ENCD + dm]);
        g_x[b*XD + EMBD + dm] = s * invS * __ldcg(&g_gate[b*ENCD + dm]);
    }
    int cap = captions[b*TT + t];
    if (tid < 32) g_x[b*XD + rank*32 + tid] = embW[cap*EMBD + rank*32 + tid];
}

// ============================================================================
// Kernel B: batched LSTM cell (weight-reuse across b).
// ============================================================================
__global__ void __launch_bounds__(256)
k6_lstm(int t,
        const float* __restrict__ Wih, const float* __restrict__ bih,
        const float* __restrict__ Whh, const float* __restrict__ bhh,
        const int* __restrict__ lens)
{
    int jc = blockIdx.x;
    int bh = blockIdx.y;
    int tid = threadIdx.x;
    int p = t & 1;
    int jbase = jc*8;
    int b0 = bh*32;

    if (t >= lens[b0]) {
        int jj = tid >> 5, bl = tid & 31;
        int idx = (b0 + bl)*DECD + jbase + jj;
        g_hbuf[1-p][idx] = g_hbuf[p][idx];
        return;
    }

    __shared__ float zt[128*36];
    __shared__ float ws[32*132];
    __shared__ float gs[32*33];

    int r = tid >> 3;
    int lane = tid & 7;
    int bl0 = lane*4;
    int grow = (r >> 3)*DECD + jbase + (r & 7);

    float acc0=0.f, acc1=0.f, acc2=0.f, acc3=0.f;
    const float* hsrc = g_hbuf[p];

    for (int kt = 0; kt < 7; kt++) {
        for (int i = tid; i < 32*128; i += 256) {
            int bl = i >> 7, k = i & 127;
            float v;
            if (kt < 3) v = g_x[(b0 + bl)*XD + kt*128 + k];
            else        v = hsrc[(b0 + bl)*DECD + (kt-3)*128 + k];
            zt[k*36 + bl] = v;
        }
        const float* Wp = (kt < 3) ? Wih : Whh;
        int kstride = (kt < 3) ? XD : DECD;
        int kb = (kt < 3) ? kt*128 : (kt-3)*128;
        for (int i = tid; i < 32*128; i += 256) {
            int rr2 = i >> 7, k = i & 127;
            int gr = (rr2 >> 3)*DECD + jbase + (rr2 & 7);
            ws[rr2*132 + k] = Wp[(size_t)gr*kstride + kb + k];
        }
        __syncthreads();
        #pragma unroll 4
        for (int k = 0; k < 128; k += 4) {
            float4 w4 = *(const float4*)&ws[r*132 + k];
            float4 za = *(const float4*)&zt[(k  )*36 + bl0];
            float4 zb = *(const float4*)&zt[(k+1)*36 + bl0];
            float4 zc = *(const float4*)&zt[(k+2)*36 + bl0];
            float4 zd = *(const float4*)&zt[(k+3)*36 + bl0];
            acc0 += w4.x*za.x + w4.y*zb.x + w4.z*zc.x + w4.w*zd.x;
            acc1 += w4.x*za.y + w4.y*zb.y + w4.z*zc.y + w4.w*zd.y;
            acc2 += w4.x*za.z + w4.y*zb.z + w4.z*zc.z + w4.w*zd.z;
            acc3 += w4.x*za.w + w4.y*zb.w + w4.z*zc.w + w4.w*zd.w;
        }
        __syncthreads();
    }
    float bias = bih[grow] + bhh[grow];
    gs[r*33 + bl0 + 0] = acc0 + bias;
    gs[r*33 + bl0 + 1] = acc1 + bias;
    gs[r*33 + bl0 + 2] = acc2 + bias;
    gs[r*33 + bl0 + 3] = acc3 + bias;
    __syncthreads();

    {
        int jj = tid >> 5, bl = tid & 31;
        int b = b0 + bl;
        int hidx = b*DECD + jbase + jj;
        if (t < lens[b]) {
            float gi = gs[( 0 + jj)*33 + bl];
            float gf = gs[( 8 + jj)*33 + bl];
            float gg = gs[(16 + jj)*33 + bl];
            float go = gs[(24 + jj)*33 + bl];
            float si = sigf(gi), sf = sigf(gf), so = sigf(go);
            float tg = tanhf(gg);
            float cn = sf * g_c[hidx] + si * tg;
            float hn = so * tanhf(cn);
            g_c[hidx] = cn;
            g_hbuf[1-p][hidx] = hn;
        } else {
            g_hbuf[1-p][hidx] = g_hbuf[p][hidx];
        }
    }
}

// ============================================================================
extern "C" void kernel_launch(void* const* d_in, const int* in_sizes, int n_in,
                              void* d_out, int out_size)
{
    const float* enc      = (const float*)d_in[0];
    const int*   captions = (const int*)  d_in[1];
    const int*   lens     = (const int*)  d_in[2];
    const float* embW     = (const float*)d_in[3];
    const float* Wenc     = (const float*)d_in[4];
    const float* benc     = (const float*)d_in[5];
    const float* Wdec     = (const float*)d_in[6];
    const float* bdec     = (const float*)d_in[7];
    const float* wfull    = (const float*)d_in[8];
    // d_in[9] = b_full : dropped (softmax shift-invariant)
    const float* Wih      = (const float*)d_in[10];
    const float* bih      = (const float*)d_in[11];
    const float* Whh      = (const float*)d_in[12];
    const float* bhh      = (const float*)d_in[13];
    const float* Winith   = (const float*)d_in[14];
    const float* binith   = (const float*)d_in[15];
    const float* Winitc   = (const float*)d_in[16];
    const float* binitc   = (const float*)d_in[17];
    const float* Wbeta    = (const float*)d_in[18];
    const float* bbeta    = (const float*)d_in[19];
    const float* Wfin     = (const float*)d_in[20];
    const float* bfin     = (const float*)d_in[21];
    float* out = (float*)d_out;

    cudaFuncSetAttribute(s_encatt, cudaFuncAttributeMaxDynamicSharedMemorySize, EA_SMEM);

    cudaMemsetAsync(d_out, 0, (size_t)out_size*sizeof(float), 0);

    s_init<<<BB, 512>>>(enc, lens, Winith, binith, Winitc, binitc, out);
    s_encatt<<<(BB*VV)/32, 256, EA_SMEM>>>(enc, Wenc, benc);

    for (int t = 0; t < TT; t++) {
        kA_step<<<dim3(CRANKS, BB), 256>>>(t, Wdec, bdec, Wbeta, bbeta, Wfin, bfin,
                                           wfull, captions, embW, lens, out);
        k6_lstm<<<dim3(64,2), 256>>>(t, Wih, bih, Whh, bhh, lens);
    }
    // final pred pass (t == len rows, incl. len == TT)
    kA_step<<<dim3(CRANKS, BB), 256>>>(TT, Wdec, bdec, Wbeta, bbeta, Wfin, bfin,
                                       wfull, captions, embW, lens, out);
}

// round 7
// speedup vs baseline: 1.6176x; 1.4763x over previous
#include <cuda_runtime.h>
#include <cuda_fp16.h>
#include <math.h>

#define BB   64
#define VV   2048
#define ENCD 128
#define TT   100
#define EMBD 256
#define DECD 512
#define ATTD 256
#define NVOC 29
#define XD   384   // EMB + ENC
#define CRANKS 8   // CTAs per cluster (one cluster per b)
#define NG   2048  // 4*DEC gate rows
#define KZ   896   // XD + DECD
#define NKC  7     // k-chunks of 128

#define PRED_OFF  0
#define ALPHA_OFF (BB*TT*NVOC)            // 185600
#define LEN_OFF   (ALPHA_OFF + BB*TT*VV)  // 13292800

// ---------------- scratch (device globals; no allocation allowed) ----------
__device__ __half g_enc_att_h[BB*VV*ATTD];  // 64 MB fp16
__device__ __half g_enc_h[BB*VV*ENCD];      // 32 MB fp16
__device__ __half g_wz[NG*KZ];              // 3.7 MB merged fp16 [W_ih | W_hh]
__device__ float  g_bz[NG];                 // merged bias
__device__ float  g_gpart[NKC*BB*NG];       // 3.7 MB gate partials [kc][b][row]
__device__ float  g_hbuf[2][BB*DECD];
__device__ float  g_c[BB*DECD];
__device__ float  g_dec_att[BB*ATTD];
__device__ float  g_gate[BB*ENCD];
__device__ float  g_part[BB*CRANKS*ENCD];
__device__ float  g_psum[BB*CRANKS];
__device__ float  g_x[BB*XD];

__device__ __forceinline__ float sigf(float x) { return 1.f/(1.f+__expf(-x)); }

#define CLUSTER_ARRIVE() asm volatile("barrier.cluster.arrive.aligned;" ::: "memory")
#define CLUSTER_WAIT()   asm volatile("barrier.cluster.wait.aligned;"   ::: "memory")

// ============================================================================
// Setup A: mean_enc -> h0,c0 ; lengths to out tail
// ============================================================================
__global__ void s_init(const float* __restrict__ enc, const int* __restrict__ lens,
                       const float* __restrict__ Wih_, const float* __restrict__ bih_,
                       const float* __restrict__ Wic_, const float* __restrict__ bic_,
                       float* __restrict__ out)
{
    int b = blockIdx.x, tid = threadIdx.x;
    __shared__ float red[16*128];
    __shared__ float mean[128];
    int vr = tid >> 5, l = tid & 31;

    float4 acc = make_float4(0.f,0.f,0.f,0.f);
    for (int v = vr; v < VV; v += 16) {
        float4 e = *(const float4*)&enc[((size_t)(b*VV + v))*ENCD + l*4];
        acc.x += e.x; acc.y += e.y; acc.z += e.z; acc.w += e.w;
    }
    *(float4*)&red[vr*128 + l*4] = acc;
    __syncthreads();
    if (tid < 128) {
        float s = 0.f;
        #pragma unroll
        for (int i = 0; i < 16; i++) s += red[i*128 + tid];
        mean[tid] = s * (1.f/(float)VV);
    }
    __syncthreads();
    float ha = bih_[tid], ca = bic_[tid];
    const float* wh = Wih_ + (size_t)tid*ENCD;
    const float* wc = Wic_ + (size_t)tid*ENCD;
    #pragma unroll 4
    for (int k = 0; k < ENCD; k++) {
        float mk = mean[k];
        ha += mk * wh[k];
        ca += mk * wc[k];
    }
    g_hbuf[0][b*DECD + tid] = ha;
    g_c[b*DECD + tid] = ca;
    if (tid == 0) out[LEN_OFF + b] = (float)lens[b];
}

// ============================================================================
// Setup W: merge LSTM weights to fp16 [row][XD | DECD], merged bias
// ============================================================================
__global__ void s_wlstm(const float* __restrict__ Wih, const float* __restrict__ bih,
                        const float* __restrict__ Whh, const float* __restrict__ bhh)
{
    int row = blockIdx.x, tid = threadIdx.x;
    for (int k = tid; k < XD; k += 256)
        g_wz[(size_t)row*KZ + k] = __float2half_rn(Wih[(size_t)row*XD + k]);
    for (int k = tid; k < DECD; k += 256)
        g_wz[(size_t)row*KZ + XD + k] = __float2half_rn(Whh[(size_t)row*DECD + k]);
    if (tid == 0) g_bz[row] = bih[row] + bhh[row];
}

// ============================================================================
// Setup B: enc_att(fp16) = enc @ W_enc.T + b_enc ; fp16 enc copy
// ============================================================================
#define EA_SMEM ((128*264 + 128*68)*4)
__global__ void __launch_bounds__(256)
s_encatt(const float* __restrict__ enc, const float* __restrict__ Wenc,
         const float* __restrict__ benc)
{
    extern __shared__ float sm[];
    float* Wt = sm;             // [128][264]
    float* Et = sm + 128*264;   // [128][68]
    int tid = threadIdx.x;
    int rowbase = blockIdx.x * 32;

    for (int i = tid; i < 256*128; i += 256) {
        int k = i & 127, a = i >> 7;
        Wt[k*264 + a] = Wenc[a*128 + k];
    }
    for (int i = tid; i < 32*128; i += 256) {
        int k = i & 127, r = i >> 7;
        Et[k*68 + r] = enc[(size_t)(rowbase + r)*128 + k];
    }
    __syncthreads();

    for (int i = tid; i < 32*128; i += 256) {
        int r = i >> 7, k = i & 127;
        g_enc_h[(size_t)(rowbase + r)*ENCD + k] = __float2half_rn(Et[k*68 + r]);
    }

    int tr = tid >> 5, ta = tid & 31;
    int r0 = tr*4, a0 = ta*8;
    float acc[4][8];
    #pragma unroll
    for (int i = 0; i < 4; i++)
        #pragma unroll
        for (int j = 0; j < 8; j++) acc[i][j] = 0.f;

    #pragma unroll 4
    for (int k = 0; k < 128; k++) {
        float4 rf = *(const float4*)&Et[k*68 + r0];
        float4 a4 = *(const float4*)&Wt[k*264 + a0];
        float4 b4 = *(const float4*)&Wt[k*264 + a0 + 4];
        float rr[4] = {rf.x, rf.y, rf.z, rf.w};
        float aa[8] = {a4.x,a4.y,a4.z,a4.w,b4.x,b4.y,b4.z,b4.w};
        #pragma unroll
        for (int i = 0; i < 4; i++)
            #pragma unroll
            for (int j = 0; j < 8; j++) acc[i][j] += rr[i]*aa[j];
    }
    float4 be0 = *(const float4*)&benc[a0];
    float4 be1 = *(const float4*)&benc[a0+4];
    float bb[8] = {be0.x,be0.y,be0.z,be0.w,be1.x,be1.y,be1.z,be1.w};
    #pragma unroll
    for (int i = 0; i < 4; i++) {
        size_t base = (size_t)(rowbase + r0 + i)*ATTD + a0;
        __half2 h[4];
        #pragma unroll
        for (int j = 0; j < 4; j++)
            h[j] = __floats2half2_rn(acc[i][2*j] + bb[2*j], acc[i][2*j+1] + bb[2*j+1]);
        *(uint4*)&g_enc_att_h[base] = *(uint4*)h;
    }
}

// ============================================================================
// Kernel A: per-b cluster of 8 CTAs (heads -> attention -> x). Unchanged.
// ============================================================================
__global__ void __cluster_dims__(CRANKS,1,1) __launch_bounds__(256)
kA_step(int t,
        const float* __restrict__ Wdec, const float* __restrict__ bdec,
        const float* __restrict__ Wbeta, const float* __restrict__ bbeta,
        const float* __restrict__ Wfin, const float* __restrict__ bfin,
        const float* __restrict__ wfull,
        const int* __restrict__ captions, const float* __restrict__ embW,
        const int* __restrict__ lens, float* __restrict__ out)
{
    int b = blockIdx.y;
    int len = lens[b];
    if (t > len) return;
    bool pred_only = (t == len);
    int rank = blockIdx.x;
    int tid = threadIdx.x;
    int warp = tid >> 5, l = tid & 31;

    __shared__ float h[512];
    __shared__ float al[256];
    __shared__ float red[8*128];
    __shared__ float wred[8];

    const float* hsrc = g_hbuf[t & 1] + b*DECD;
    h[tid]       = hsrc[tid];
    h[tid + 256] = hsrc[tid + 256];
    __syncthreads();

    {
        int g = tid >> 2, sub = tid & 3;
        int row_real = rank*52 + g;
        int row = row_real < 413 ? row_real : 412;
        const float* wrow; float bias; int kind;
        if (row < 256)      { wrow = Wdec  + (size_t)row*DECD;       bias = bdec[row];      kind = 0; }
        else if (row < 384) { wrow = Wbeta + (size_t)(row-256)*DECD; bias = bbeta[row-256]; kind = 1; }
        else                { wrow = Wfin  + (size_t)(row-384)*DECD; bias = bfin[row-384];  kind = 2; }

        float acc = 0.f;
        #pragma unroll 8
        for (int i = 0; i < 32; i++) {
            int k = sub*4 + i*16;
            float4 w  = *(const float4*)&wrow[k];
            float4 hz = *(const float4*)&h[k];
            acc += w.x*hz.x + w.y*hz.y + w.z*hz.z + w.w*hz.w;
        }
        acc += __shfl_xor_sync(0xffffffffu, acc, 1);
        acc += __shfl_xor_sync(0xffffffffu, acc, 2);
        if (sub == 0 && g < 52 && row_real < 413) {
            acc += bias;
            if (kind == 0)      g_dec_att[b*ATTD + row] = acc;
            else if (kind == 1) g_gate[b*ENCD + (row-256)] = sigf(acc);
            else if (t > 0)     out[PRED_OFF + ((size_t)b*TT + (t-1))*NVOC + (row-384)] = acc;
        }
    }
    if (pred_only) return;
    __threadfence();
    CLUSTER_ARRIVE(); CLUSTER_WAIT();

    int vbase = rank*256;
    int a0 = l*8;
    __half2 d2[4]; float w[8];
    {
        float da[8];
        #pragma unroll
        for (int j = 0; j < 8; j++) da[j] = __ldcg(&g_dec_att[b*ATTD + a0 + j]);
        d2[0] = __floats2half2_rn(da[0], da[1]);
        d2[1] = __floats2half2_rn(da[2], da[3]);
        d2[2] = __floats2half2_rn(da[4], da[5]);
        d2[3] = __floats2half2_rn(da[6], da[7]);
        float4 ww0 = *(const float4*)&wfull[a0];
        float4 ww1 = *(const float4*)&wfull[a0 + 4];
        w[0]=ww0.x; w[1]=ww0.y; w[2]=ww0.z; w[3]=ww0.w;
        w[4]=ww1.x; w[5]=ww1.y; w[6]=ww1.z; w[7]=ww1.w;
    }
    const __half2 z2 = __float2half2_rn(0.f);
    const __half* ea = g_enc_att_h + ((size_t)(b*VV + vbase))*ATTD;

    #pragma unroll
    for (int i = 0; i < 32; i += 4) {
        uint4 q[4];
        #pragma unroll
        for (int u = 0; u < 4; u++)
            q[u] = *(const uint4*)&ea[(size_t)((i+u)*8 + warp)*ATTD + a0];
        float s[4];
        #pragma unroll
        for (int u = 0; u < 4; u++) {
            const __half2* hh = (const __half2*)&q[u];
            float acc = 0.f;
            #pragma unroll
            for (int j = 0; j < 4; j++) {
                __half2 v = __hmax2(__hadd2(hh[j], d2[j]), z2);
                float2 f = __half22float2(v);
                acc += f.x*w[2*j] + f.y*w[2*j+1];
            }
            s[u] = acc;
        }
        #pragma unroll
        for (int o = 16; o; o >>= 1) {
            #pragma unroll
            for (int u = 0; u < 4; u++)
                s[u] += __shfl_xor_sync(0xffffffffu, s[u], o);
        }
        if (l == 0) {
            #pragma unroll
            for (int u = 0; u < 4; u++) al[(i+u)*8 + warp] = __expf(s[u]);
        }
    }
    __syncthreads();

    {
        float e = al[tid];
        #pragma unroll
        for (int o = 16; o; o >>= 1) e += __shfl_xor_sync(0xffffffffu, e, o);
        if (l == 0) wred[warp] = e;
    }

    const __half* eh = g_enc_h + ((size_t)(b*VV + vbase))*ENCD;
    float4 acc = make_float4(0.f,0.f,0.f,0.f);
    #pragma unroll 4
    for (int i = 0; i < 32; i++) {
        int r = i*8 + warp;
        float a = al[r];
        uint2 q = *(const uint2*)&eh[(size_t)r*ENCD + l*4];
        float2 e0 = __half22float2(((const __half2*)&q)[0]);
        float2 e1 = __half22float2(((const __half2*)&q)[1]);
        acc.x += a*e0.x; acc.y += a*e0.y; acc.z += a*e1.x; acc.w += a*e1.y;
    }
    *(float4*)&red[warp*128 + l*4] = acc;
    __syncthreads();
    if (tid < 128) {
        float s = 0.f;
        #pragma unroll
        for (int i = 0; i < 8; i++) s += red[i*128 + tid];
        g_part[(b*CRANKS + rank)*ENCD + tid] = s;
    }
    if (tid == 0) {
        float ss = 0.f;
        #pragma unroll
        for (int i = 0; i < 8; i++) ss += wred[i];
        g_psum[b*CRANKS + rank] = ss;
    }
    __threadfence();
    CLUSTER_ARRIVE(); CLUSTER_WAIT();

    if (tid < CRANKS) wred[tid] = __ldcg(&g_psum[b*CRANKS + tid]);
    __syncthreads();
    float S = 0.f;
    #pragma unroll
    for (int i = 0; i < CRANKS; i++) S += wred[i];
    float invS = 1.f/S;

    out[ALPHA_OFF + ((size_t)b*TT + t)*VV + vbase + tid] = al[tid] * invS;

    if (tid < 16) {
        int dm = rank*16 + tid;
        float s = 0.f;
        #pragma unroll
        for (int r = 0; r < CRANKS; r++) s += __ldcg(&g_part[(b*CRANKS + r)*ENCD + dm]);
        g_x[b*XD + EMBD + dm] = s * invS * __ldcg(&g_gate[b*ENCD + dm]);
    }
    int cap = captions[b*TT + t];
    if (tid < 32) g_x[b*XD + rank*32 + tid] = embW[cap*EMBD + rank*32 + tid];
}

// ============================================================================
// K6a: split-K LSTM GEMM.  grid(7, 32): kc-chunk x 64-row chunk, block 256.
// 64 rows x 128 k x 64 b tile; fp16 weights, fp32 accumulate.
// partials -> g_gpart[kc][b][row]
// ============================================================================
__global__ void __launch_bounds__(256)
k6a_gemm(int t, const int* __restrict__ lens)
{
    int kc = blockIdx.x, rc = blockIdx.y, tid = threadIdx.x;
    __shared__ float wt[128*68];   // [k][r]
    __shared__ float zt[128*68];   // [k][b]

    int pred = (tid < 64) && (t < lens[tid]);
    int nb = __syncthreads_count(pred);   // active batch prefix (lens sorted desc)

    const float* hsrc = g_hbuf[t & 1];
    int kbase = kc * 128;
    int rowbase = rc * 64;

    // weight tile: 64 rows x 128 halves
    for (int i = tid; i < 64*64; i += 256) {
        int r = i >> 6, kp = i & 63;
        unsigned int u = *(const unsigned int*)&g_wz[(size_t)(rowbase + r)*KZ + kbase + kp*2];
        float2 f = __half22float2(*(const __half2*)&u);
        wt[(kp*2  )*68 + r] = f.x;
        wt[(kp*2+1)*68 + r] = f.y;
    }
    // z tile: [k][b]
    for (int i = tid; i < 64*128; i += 256) {
        int b = i >> 7, k = i & 127;
        int gk = kbase + k;
        float v = (gk < XD) ? g_x[b*XD + gk] : hsrc[b*DECD + (gk - XD)];
        zt[k*68 + b] = v;
    }
    __syncthreads();

    int r0 = (tid & 15) * 4;
    int b0 = (tid >> 4) * 4;
    if (b0 >= nb) return;

    float acc[4][4];
    #pragma unroll
    for (int i = 0; i < 4; i++)
        #pragma unroll
        for (int j = 0; j < 4; j++) acc[i][j] = 0.f;

    #pragma unroll 4
    for (int k = 0; k < 128; k++) {
        float4 w = *(const float4*)&wt[k*68 + r0];
        float4 z = *(const float4*)&zt[k*68 + b0];
        float ww[4] = {w.x, w.y, w.z, w.w};
        float zz[4] = {z.x, z.y, z.z, z.w};
        #pragma unroll
        for (int i = 0; i < 4; i++)
            #pragma unroll
            for (int j = 0; j < 4; j++) acc[i][j] += ww[i]*zz[j];
    }
    #pragma unroll
    for (int j = 0; j < 4; j++) {
        *(float4*)&g_gpart[((size_t)(kc*BB + b0 + j))*NG + rowbase + r0] =
            make_float4(acc[0][j], acc[1][j], acc[2][j], acc[3][j]);
    }
}

// ============================================================================
// K6b: combine partials + bias -> activations -> c,h update (masked copy)
// grid(64) = b, block(512) = j.
// ============================================================================
__global__ void __launch_bounds__(512)
k6b_cell(int t, const int* __restrict__ lens)
{
    int b = blockIdx.x, j = threadIdx.x;
    int p = t & 1;
    int hidx = b*DECD + j;
    if (t < lens[b]) {
        float g4[4];
        #pragma unroll
        for (int g = 0; g < 4; g++) {
            int row = g*DECD + j;
            float s = g_bz[row];
            #pragma unroll
            for (int kc = 0; kc < NKC; kc++)
                s += g_gpart[((size_t)(kc*BB + b))*NG + row];
            g4[g] = s;
        }
        float si = sigf(g4[0]), sf = sigf(g4[1]), tg = tanhf(g4[2]), so = sigf(g4[3]);
        float cn = sf * g_c[hidx] + si * tg;
        g_c[hidx] = cn;
        g_hbuf[1-p][hidx] = so * tanhf(cn);
    } else {
        g_hbuf[1-p][hidx] = g_hbuf[p][hidx];
    }
}

// ============================================================================
extern "C" void kernel_launch(void* const* d_in, const int* in_sizes, int n_in,
                              void* d_out, int out_size)
{
    const float* enc      = (const float*)d_in[0];
    const int*   captions = (const int*)  d_in[1];
    const int*   lens     = (const int*)  d_in[2];
    const float* embW     = (const float*)d_in[3];
    const float* Wenc     = (const float*)d_in[4];
    const float* benc     = (const float*)d_in[5];
    const float* Wdec     = (const float*)d_in[6];
    const float* bdec     = (const float*)d_in[7];
    const float* wfull    = (const float*)d_in[8];
    // d_in[9] = b_full : dropped (softmax shift-invariant)
    const float* Wih      = (const float*)d_in[10];
    const float* bih      = (const float*)d_in[11];
    const float* Whh      = (const float*)d_in[12];
    const float* bhh      = (const float*)d_in[13];
    const float* Winith   = (const float*)d_in[14];
    const float* binith   = (const float*)d_in[15];
    const float* Winitc   = (const float*)d_in[16];
    const float* binitc   = (const float*)d_in[17];
    const float* Wbeta    = (const float*)d_in[18];
    const float* bbeta    = (const float*)d_in[19];
    const float* Wfin     = (const float*)d_in[20];
    const float* bfin     = (const float*)d_in[21];
    float* out = (float*)d_out;

    cudaFuncSetAttribute(s_encatt, cudaFuncAttributeMaxDynamicSharedMemorySize, EA_SMEM);

    cudaMemsetAsync(d_out, 0, (size_t)out_size*sizeof(float), 0);

    s_init<<<BB, 512>>>(enc, lens, Winith, binith, Winitc, binitc, out);
    s_wlstm<<<NG, 256>>>(Wih, bih, Whh, bhh);
    s_encatt<<<(BB*VV)/32, 256, EA_SMEM>>>(enc, Wenc, benc);

    for (int t = 0; t < TT; t++) {
        kA_step<<<dim3(CRANKS, BB), 256>>>(t, Wdec, bdec, Wbeta, bbeta, Wfin, bfin,
                                           wfull, captions, embW, lens, out);
        k6a_gemm<<<dim3(NKC, 32), 256>>>(t, lens);
        k6b_cell<<<BB, 512>>>(t, lens);
    }
    kA_step<<<dim3(CRANKS, BB), 256>>>(TT, Wdec, bdec, Wbeta, bbeta, Wfin, bfin,
                                       wfull, captions, embW, lens, out);
}